// round 2
// baseline (speedup 1.0000x reference)
#include <cuda_runtime.h>
#include <math.h>

#define B_   64
#define N_   197
#define C_   768
#define H_   12
#define HD_  64
#define BH_  (B_*H_)            // 768
#define MROWS (B_*N_)           // 12608
#define MASK_NEG_ -100000.0f

// ---------------- scratch ----------------
__device__ float g_q[(size_t)BH_*N_*HD_];   // scaled q, [b,h,n,d]
__device__ float g_k[(size_t)BH_*N_*HD_];
__device__ float g_v[(size_t)BH_*N_*HD_];
__device__ float g_ctx[(size_t)MROWS*C_];   // [b,n,h,d] == [m, C]
__device__ float g_mask[B_*N_];             // additive mask

// ---------------- GEMM: out[M,N] = A[M,K] @ W[N,K]^T + bias ----------------
// MODE 0: A = x, scatter into g_q/g_k/g_v (q scaled). MODE 1: A = g_ctx, write to out.
#define BM 128
#define BN 128
#define BK 16

template<int MODE>
__global__ __launch_bounds__(256)
void gemm_bias(const float* __restrict__ A_in, const float* __restrict__ W,
               const float* __restrict__ bias, float* __restrict__ out,
               int M, int N, int K)
{
    const float* A = (MODE == 1) ? g_ctx : A_in;

    __shared__ float As[BK][BM];
    __shared__ float Bs[BK][BN];

    const int tid = threadIdx.x;
    const int bm  = blockIdx.y * BM;
    const int bn  = blockIdx.x * BN;

    const int lr = tid >> 2;            // 0..63
    const int lc = (tid & 3) << 2;      // 0,4,8,12

    const int ty = tid >> 4;            // 0..15
    const int tx = tid & 15;            // 0..15

    float acc[8][8];
#pragma unroll
    for (int i = 0; i < 8; i++)
#pragma unroll
        for (int j = 0; j < 8; j++) acc[i][j] = 0.f;

    for (int k0 = 0; k0 < K; k0 += BK) {
#pragma unroll
        for (int s = 0; s < 2; s++) {
            int row = lr + s * 64;
            int gm  = bm + row;
            float4 v;
            if (gm < M) v = *reinterpret_cast<const float4*>(A + (size_t)gm * K + k0 + lc);
            else        v = make_float4(0.f, 0.f, 0.f, 0.f);
            As[lc+0][row] = v.x; As[lc+1][row] = v.y;
            As[lc+2][row] = v.z; As[lc+3][row] = v.w;
        }
#pragma unroll
        for (int s = 0; s < 2; s++) {
            int row = lr + s * 64;
            int gn  = bn + row;       // always in-bounds (N multiple of 128)
            float4 v = *reinterpret_cast<const float4*>(W + (size_t)gn * K + k0 + lc);
            Bs[lc+0][row] = v.x; Bs[lc+1][row] = v.y;
            Bs[lc+2][row] = v.z; Bs[lc+3][row] = v.w;
        }
        __syncthreads();

#pragma unroll
        for (int kk = 0; kk < BK; kk++) {
            float a[8], b[8];
#pragma unroll
            for (int i = 0; i < 8; i++) a[i] = As[kk][ty*8 + i];
#pragma unroll
            for (int j = 0; j < 8; j++) b[j] = Bs[kk][tx*8 + j];
#pragma unroll
            for (int i = 0; i < 8; i++)
#pragma unroll
                for (int j = 0; j < 8; j++)
                    acc[i][j] += a[i] * b[j];
        }
        __syncthreads();
    }

#pragma unroll
    for (int i = 0; i < 8; i++) {
        int m = bm + ty*8 + i;
        if (m >= M) continue;
        int bb = m / N_;
        int nn = m - bb * N_;
#pragma unroll
        for (int j = 0; j < 8; j++) {
            int c = bn + tx*8 + j;
            float val = acc[i][j] + bias[c];
            if (MODE == 0) {
                int part = c / C_;
                int rem  = c - part * C_;
                int h = rem >> 6;
                int d = rem & 63;
                size_t idx = ((size_t)(bb * H_ + h) * N_ + nn) * HD_ + d;
                if      (part == 0) g_q[idx] = val * 0.125f;   // hd^-0.5
                else if (part == 1) g_k[idx] = val;
                else                g_v[idx] = val;
            } else {
                out[(size_t)m * N + c] = val;
            }
        }
    }
}

// ---------------- attn_rt = q @ k^T (q pre-scaled), per (b,h) 197x197 ----------------
__global__ __launch_bounds__(256)
void attn_scores(float* __restrict__ attn)
{
    __shared__ float Qs[HD_][65];
    __shared__ float Ks[HD_][65];

    const int bh = blockIdx.z;
    const int qt = blockIdx.y * 64;
    const int kt = blockIdx.x * 64;
    const int tid = threadIdx.x;

    const float* qb = g_q + (size_t)bh * N_ * HD_;
    const float* kb = g_k + (size_t)bh * N_ * HD_;

    const int lr = tid >> 4;            // 0..15
    const int lc = (tid & 15) << 2;     // 0..60 step 4

#pragma unroll
    for (int s = 0; s < 4; s++) {
        int row = lr + s * 16;
        float4 v;
        int gq = qt + row;
        if (gq < N_) v = *reinterpret_cast<const float4*>(qb + (size_t)gq * HD_ + lc);
        else         v = make_float4(0.f, 0.f, 0.f, 0.f);
        Qs[lc+0][row] = v.x; Qs[lc+1][row] = v.y;
        Qs[lc+2][row] = v.z; Qs[lc+3][row] = v.w;

        int gk = kt + row;
        if (gk < N_) v = *reinterpret_cast<const float4*>(kb + (size_t)gk * HD_ + lc);
        else         v = make_float4(0.f, 0.f, 0.f, 0.f);
        Ks[lc+0][row] = v.x; Ks[lc+1][row] = v.y;
        Ks[lc+2][row] = v.z; Ks[lc+3][row] = v.w;
    }
    __syncthreads();

    const int ty = tid >> 4, tx = tid & 15;
    float acc[4][4] = {};
#pragma unroll
    for (int kk = 0; kk < HD_; kk++) {
        float a[4], b[4];
#pragma unroll
        for (int i = 0; i < 4; i++) a[i] = Qs[kk][ty*4 + i];
#pragma unroll
        for (int j = 0; j < 4; j++) b[j] = Ks[kk][tx*4 + j];
#pragma unroll
        for (int i = 0; i < 4; i++)
#pragma unroll
            for (int j = 0; j < 4; j++)
                acc[i][j] += a[i] * b[j];
    }

    float* ab = attn + (size_t)bh * N_ * N_;
#pragma unroll
    for (int i = 0; i < 4; i++) {
        int qi = qt + ty*4 + i;
        if (qi >= N_) continue;
#pragma unroll
        for (int j = 0; j < 4; j++) {
            int kj = kt + tx*4 + j;
            if (kj < N_) ab[(size_t)qi * N_ + kj] = acc[i][j];
        }
    }
}

// ---------------- cls scores, exact top-k rank, mask + keep_mask ----------------
__global__ __launch_bounds__(256)
void topk_mask(const float* __restrict__ attn, float* __restrict__ keep_out,
               const int* __restrict__ num_keep)
{
    __shared__ float s[196];
    const int b = blockIdx.x;
    const int t = threadIdx.x;
    const int k = num_keep[0];

    if (t < 196) {
        float sum = 0.f;
        const float* base = attn + (size_t)b * H_ * N_ * N_ + (t + 1); // row 0, col t+1
#pragma unroll
        for (int h = 0; h < H_; h++) sum += base[(size_t)h * N_ * N_];
        s[t] = sum * (1.0f / 12.0f);
    }
    __syncthreads();

    if (t < 196) {
        float mine = s[t];
        int rank = 0;
        for (int i = 0; i < 196; i++) {
            float si = s[i];
            rank += (si > mine) || (si == mine && i < t);
        }
        bool keep = rank < k;
        g_mask[b * N_ + t + 1]   = keep ? 0.f : MASK_NEG_;
        keep_out[b * N_ + t + 1] = keep ? 1.f : 0.f;
    }
    if (t == 0) {
        g_mask[b * N_]   = 0.f;   // cls always kept
        keep_out[b * N_] = 1.f;
    }
}

// ---------------- masked softmax + attn @ V -> ctx[b,n,h,d] ----------------
// dyn smem: Vs[197*64] | msk[197] | prows[32*197]
__global__ __launch_bounds__(256)
void softmax_av(const float* __restrict__ attn)
{
    extern __shared__ float smem[];
    float* Vs    = smem;                 // 12608
    float* msk   = Vs + N_ * HD_;        // 197
    float* prows = msk + N_;             // 32*197

    const int bh = blockIdx.x;
    const int b  = bh / H_;
    const int h  = bh - b * H_;
    const int tid = threadIdx.x;

    const float* vb = g_v + (size_t)bh * N_ * HD_;
    for (int i = tid; i < (N_ * HD_) / 4; i += 256)
        reinterpret_cast<float4*>(Vs)[i] = reinterpret_cast<const float4*>(vb)[i];
    for (int i = tid; i < N_; i += 256) msk[i] = g_mask[b * N_ + i];
    __syncthreads();

    const int w = tid >> 5, lane = tid & 31;
    const float* ab = attn + (size_t)bh * N_ * N_;

    for (int base = w * 4; base < N_; base += 32) {
        float xv[4][7];
        float mx[4] = {-1e30f, -1e30f, -1e30f, -1e30f};
#pragma unroll
        for (int r = 0; r < 4; r++) {
            int row = base + r;
            if (row >= N_) continue;
            const float* arow = ab + (size_t)row * N_;
#pragma unroll
            for (int t = 0; t < 7; t++) {
                int j = lane + t * 32;
                float x = (j < N_) ? (arow[j] + msk[j]) : -1e30f;
                xv[r][t] = x;
                mx[r] = fmaxf(mx[r], x);
            }
        }
#pragma unroll
        for (int r = 0; r < 4; r++)
            for (int o = 16; o > 0; o >>= 1)
                mx[r] = fmaxf(mx[r], __shfl_xor_sync(0xffffffffu, mx[r], o));

        float sum[4] = {0.f, 0.f, 0.f, 0.f};
#pragma unroll
        for (int r = 0; r < 4; r++) {
            int row = base + r;
            if (row >= N_) continue;
            float* pr = prows + (w * 4 + r) * N_;
#pragma unroll
            for (int t = 0; t < 7; t++) {
                int j = lane + t * 32;
                if (j < N_) {
                    float e = __expf(xv[r][t] - mx[r]);
                    pr[j] = e;
                    sum[r] += e;
                }
            }
        }
#pragma unroll
        for (int r = 0; r < 4; r++)
            for (int o = 16; o > 0; o >>= 1)
                sum[r] += __shfl_xor_sync(0xffffffffu, sum[r], o);

        __syncwarp();

        float acc0[4] = {0.f,0.f,0.f,0.f}, acc1[4] = {0.f,0.f,0.f,0.f};
        const float* pr0 = prows + (w * 4 + 0) * N_;
        const float* pr1 = prows + (w * 4 + 1) * N_;
        const float* pr2 = prows + (w * 4 + 2) * N_;
        const float* pr3 = prows + (w * 4 + 3) * N_;
        for (int j = 0; j < N_; j++) {
            float v0 = Vs[j * HD_ + lane];
            float v1 = Vs[j * HD_ + lane + 32];
            float p0 = pr0[j], p1 = pr1[j], p2 = pr2[j], p3 = pr3[j];
            acc0[0] += p0 * v0; acc1[0] += p0 * v1;
            acc0[1] += p1 * v0; acc1[1] += p1 * v1;
            acc0[2] += p2 * v0; acc1[2] += p2 * v1;
            acc0[3] += p3 * v0; acc1[3] += p3 * v1;
        }
#pragma unroll
        for (int r = 0; r < 4; r++) {
            int row = base + r;
            if (row >= N_) continue;
            float inv = 1.f / sum[r];
            size_t o = ((size_t)(b * N_ + row) * H_ + h) * HD_;
            g_ctx[o + lane]      = acc0[r] * inv;
            g_ctx[o + lane + 32] = acc1[r] * inv;
        }
        __syncwarp();
    }
}

// ---------------- launch ----------------
extern "C" void kernel_launch(void* const* d_in, const int* in_sizes, int n_in,
                              void* d_out, int out_size)
{
    const float* x      = (const float*)d_in[0];
    const float* qkv_w  = (const float*)d_in[1];
    const float* qkv_b  = (const float*)d_in[2];
    const float* proj_w = (const float*)d_in[3];
    const float* proj_b = (const float*)d_in[4];
    const int*   nkeep  = (const int*)  d_in[5];

    float* out       = (float*)d_out;                       // [B,N,C]
    float* keep_mask = out + (size_t)MROWS * C_;            // [B,N,1]
    float* attn      = keep_mask + MROWS;                   // [B,H,N,N]

    const int SMEM4 = (N_ * HD_ + N_ + 32 * N_) * (int)sizeof(float); // 76436
    cudaFuncSetAttribute((const void*)softmax_av,
                         cudaFuncAttributeMaxDynamicSharedMemorySize, SMEM4);

    // 1) qkv GEMM -> g_q (scaled), g_k, g_v
    gemm_bias<0><<<dim3((3 * C_) / BN, (MROWS + BM - 1) / BM), 256>>>(
        x, qkv_w, qkv_b, nullptr, MROWS, 3 * C_, C_);

    // 2) attn_rt = q @ k^T, written directly into output region
    attn_scores<<<dim3(4, 4, BH_), 256>>>(attn);

    // 3) cls mean + top-k -> additive mask + keep_mask output
    topk_mask<<<B_, 256>>>(attn, keep_mask, nkeep);

    // 4) masked softmax + attn @ V -> g_ctx [b,n,h,d]
    softmax_av<<<BH_, 256, SMEM4>>>(attn);

    // 5) proj GEMM -> out
    gemm_bias<1><<<dim3(C_ / BN, (MROWS + BM - 1) / BM), 256>>>(
        nullptr, proj_w, proj_b, out, MROWS, C_, C_);
}

// round 4
// speedup vs baseline: 1.1603x; 1.1603x over previous
#include <cuda_runtime.h>
#include <cstdint>
#include <math.h>

#define B_   64
#define N_   197
#define C_   768
#define H_   12
#define HD_  64
#define BH_  (B_*H_)            // 768
#define MROWS (B_*N_)           // 12608
#define MASK_NEG_ -100000.0f

// ---------------- scratch ----------------
__device__ __align__(16) float g_q[(size_t)BH_*N_*HD_];   // scaled q, [b,h,n,d]
__device__ __align__(16) float g_k[(size_t)BH_*N_*HD_];
__device__ __align__(16) float g_v[(size_t)BH_*N_*HD_];
__device__ __align__(16) float g_ctx[(size_t)MROWS*C_];   // [b,n,h,d] == [m, C]
__device__ float g_mask[B_*N_];                           // additive mask

// ================= tf32 helpers =================
__device__ __forceinline__ uint32_t f2tf32u(float x) {
    uint32_t u;
    asm("cvt.rna.tf32.f32 %0, %1;" : "=r"(u) : "f"(x));
    return u;
}

__device__ __forceinline__ void mma_tf32(float acc[4], const uint32_t a[4], const uint32_t b[2]) {
    asm volatile("mma.sync.aligned.m16n8k8.row.col.f32.tf32.tf32.f32 "
        "{%0,%1,%2,%3}, {%4,%5,%6,%7}, {%8,%9}, {%0,%1,%2,%3};"
        : "+f"(acc[0]), "+f"(acc[1]), "+f"(acc[2]), "+f"(acc[3])
        : "r"(a[0]), "r"(a[1]), "r"(a[2]), "r"(a[3]), "r"(b[0]), "r"(b[1]));
}

// smem float layout: bias[128] | A0[4096] | A1[4096] | Bh0[4096] | Bh1[4096] | Bl0[4096] | Bl1[4096]
#define GEMM_SMEM_FLOATS (128 + 6*4096)
#define GEMM_SMEM_BYTES  (GEMM_SMEM_FLOATS * 4)   // 98816

// ================= 3xTF32 mma.sync GEMM =================
// out[M,N] = A[M,K] @ W[N,K]^T + bias.  MODE 0: A=x, scatter q/k/v. MODE 1: A=g_ctx -> out.
template<int MODE>
__global__ __launch_bounds__(256, 2)
void gemm_mma(const float* __restrict__ A_in, const float* __restrict__ W,
              const float* __restrict__ bias, float* __restrict__ out,
              int M, int N, int K)
{
    const float* A = (MODE == 1) ? g_ctx : A_in;
    extern __shared__ float sm[];
    float* s_bias = sm;
    float* sA0  = sm + 128;
    float* sA1  = sm + 128 + 4096;
    float* sBh0 = sm + 128 + 8192;
    float* sBh1 = sm + 128 + 12288;
    float* sBl0 = sm + 128 + 16384;
    float* sBl1 = sm + 128 + 20480;

    const int tid   = threadIdx.x;
    const int lane  = tid & 31;
    const int wid   = tid >> 5;
    const int warp_m = wid & 1;     // 0..1  -> 64 rows
    const int warp_n = wid >> 1;    // 0..3  -> 32 cols
    const int bm = blockIdx.y * 128, bn = blockIdx.x * 128;

    if (tid < 128) s_bias[tid] = bias[bn + tid];

    float acc[4][4][4];
#pragma unroll
    for (int i = 0; i < 4; i++)
#pragma unroll
        for (int j = 0; j < 4; j++)
#pragma unroll
            for (int r = 0; r < 4; r++) acc[i][j][r] = 0.f;

    // ---- loader: raw A (fragment layout), B split hi/lo (fragment layout) ----
    auto load_stage = [&](float* dA, float* dBh, float* dBl, int k0) {
#pragma unroll
        for (int it = 0; it < 4; it++) {
            int linear = tid + it * 256;         // 0..1023
            int row = linear >> 3;               // 0..127
            int c0  = (linear & 7) << 2;         // 0..28 step 4
            int ksl = c0 >> 3;                   // k8-step
            int ccb = c0 & 7;                    // 0 or 4

            // A tile (raw fp32 in m16k8 fragment layout)
            int gm = bm + row;
            float4 v = make_float4(0.f, 0.f, 0.f, 0.f);
            if (gm < M) v = *reinterpret_cast<const float4*>(A + (size_t)gm * K + k0 + c0);
            {
                int mt = row >> 4, rr = row & 15;
                int rbase = (rr >> 3) | ((ccb >> 2) << 1);
                float* da = dA + (mt * 4 + ksl) * 128 + ((rr & 7) * 4) * 4 + rbase;
                da[0]  = v.x; da[4]  = v.y; da[8]  = v.z; da[12] = v.w;
            }

            // B tile (tf32 hi/lo in k8n8 fragment layout)
            float4 w4 = *reinterpret_cast<const float4*>(W + (size_t)(bn + row) * K + k0 + c0);
            {
                int nt = row >> 3, nn = row & 7;
                int rb = ccb >> 2;
                int boff = (nt * 4 + ksl) * 64 + nn * 8 + rb;
                uint32_t h0 = f2tf32u(w4.x), h1 = f2tf32u(w4.y),
                         h2 = f2tf32u(w4.z), h3 = f2tf32u(w4.w);
                uint32_t l0 = f2tf32u(w4.x - __uint_as_float(h0));
                uint32_t l1 = f2tf32u(w4.y - __uint_as_float(h1));
                uint32_t l2 = f2tf32u(w4.z - __uint_as_float(h2));
                uint32_t l3 = f2tf32u(w4.w - __uint_as_float(h3));
                dBh[boff + 0] = __uint_as_float(h0); dBh[boff + 2] = __uint_as_float(h1);
                dBh[boff + 4] = __uint_as_float(h2); dBh[boff + 6] = __uint_as_float(h3);
                dBl[boff + 0] = __uint_as_float(l0); dBl[boff + 2] = __uint_as_float(l1);
                dBl[boff + 4] = __uint_as_float(l2); dBl[boff + 6] = __uint_as_float(l3);
            }
        }
    };

    auto compute_stage = [&](const float* cA, const float* cBh, const float* cBl) {
#pragma unroll
        for (int ks = 0; ks < 4; ks++) {
            uint32_t ah[4][4], al[4][4];
#pragma unroll
            for (int im = 0; im < 4; im++) {
                int mt = warp_m * 4 + im;
                float4 a = *reinterpret_cast<const float4*>(cA + (mt * 4 + ks) * 128 + lane * 4);
                ah[im][0] = f2tf32u(a.x); al[im][0] = f2tf32u(a.x - __uint_as_float(ah[im][0]));
                ah[im][1] = f2tf32u(a.y); al[im][1] = f2tf32u(a.y - __uint_as_float(ah[im][1]));
                ah[im][2] = f2tf32u(a.z); al[im][2] = f2tf32u(a.z - __uint_as_float(ah[im][2]));
                ah[im][3] = f2tf32u(a.w); al[im][3] = f2tf32u(a.w - __uint_as_float(ah[im][3]));
            }
            uint32_t bh[4][2], bl[4][2];
#pragma unroll
            for (int jn = 0; jn < 4; jn++) {
                int nt = warp_n * 4 + jn;
                float2 h = *reinterpret_cast<const float2*>(cBh + (nt * 4 + ks) * 64 + lane * 2);
                float2 l = *reinterpret_cast<const float2*>(cBl + (nt * 4 + ks) * 64 + lane * 2);
                bh[jn][0] = __float_as_uint(h.x); bh[jn][1] = __float_as_uint(h.y);
                bl[jn][0] = __float_as_uint(l.x); bl[jn][1] = __float_as_uint(l.y);
            }
#pragma unroll
            for (int im = 0; im < 4; im++)
#pragma unroll
                for (int jn = 0; jn < 4; jn++) {
                    mma_tf32(acc[im][jn], al[im], bh[jn]);
                    mma_tf32(acc[im][jn], ah[im], bl[jn]);
                    mma_tf32(acc[im][jn], ah[im], bh[jn]);
                }
        }
    };

    load_stage(sA0, sBh0, sBl0, 0);
    __syncthreads();

    const int nchunk = K >> 5;   // 24
    for (int c = 0; c < nchunk; c++) {
        const int st = c & 1;
        if (c + 1 < nchunk) {
            if (st == 0) load_stage(sA1, sBh1, sBl1, (c + 1) << 5);
            else         load_stage(sA0, sBh0, sBl0, (c + 1) << 5);
        }
        if (st == 0) compute_stage(sA0, sBh0, sBl0);
        else         compute_stage(sA1, sBh1, sBl1);
        __syncthreads();
    }

    // ---- epilogue ----
#pragma unroll
    for (int im = 0; im < 4; im++) {
        int row0 = warp_m * 64 + im * 16 + (lane >> 2);
#pragma unroll
        for (int jn = 0; jn < 4; jn++) {
            int col0 = warp_n * 32 + jn * 8 + (lane & 3) * 2;
#pragma unroll
            for (int r = 0; r < 4; r++) {
                int m  = bm + row0 + ((r >= 2) ? 8 : 0);
                int cl = col0 + (r & 1);
                if (m >= M) continue;
                int cc = bn + cl;
                float val = acc[im][jn][r] + s_bias[cl];
                if (MODE == 0) {
                    int bb = m / N_;
                    int nn2 = m - bb * N_;
                    int part = cc / C_;
                    int rem  = cc - part * C_;
                    int h = rem >> 6;
                    int dd = rem & 63;
                    size_t idx = ((size_t)(bb * H_ + h) * N_ + nn2) * HD_ + dd;
                    if      (part == 0) g_q[idx] = val * 0.125f;
                    else if (part == 1) g_k[idx] = val;
                    else                g_v[idx] = val;
                } else {
                    out[(size_t)m * N + cc] = val;
                }
            }
        }
    }
}

// ---------------- attn_rt = q @ k^T (q pre-scaled), per (b,h) 197x197 ----------------
__global__ __launch_bounds__(256)
void attn_scores(float* __restrict__ attn)
{
    __shared__ float Qs[HD_][65];
    __shared__ float Ks[HD_][65];

    const int bh = blockIdx.z;
    const int qt = blockIdx.y * 64;
    const int kt = blockIdx.x * 64;
    const int tid = threadIdx.x;

    const float* qb = g_q + (size_t)bh * N_ * HD_;
    const float* kb = g_k + (size_t)bh * N_ * HD_;

    const int lr = tid >> 4;
    const int lc = (tid & 15) << 2;

#pragma unroll
    for (int s = 0; s < 4; s++) {
        int row = lr + s * 16;
        float4 v;
        int gq = qt + row;
        if (gq < N_) v = *reinterpret_cast<const float4*>(qb + (size_t)gq * HD_ + lc);
        else         v = make_float4(0.f, 0.f, 0.f, 0.f);
        Qs[lc+0][row] = v.x; Qs[lc+1][row] = v.y;
        Qs[lc+2][row] = v.z; Qs[lc+3][row] = v.w;

        int gk = kt + row;
        if (gk < N_) v = *reinterpret_cast<const float4*>(kb + (size_t)gk * HD_ + lc);
        else         v = make_float4(0.f, 0.f, 0.f, 0.f);
        Ks[lc+0][row] = v.x; Ks[lc+1][row] = v.y;
        Ks[lc+2][row] = v.z; Ks[lc+3][row] = v.w;
    }
    __syncthreads();

    const int ty = tid >> 4, tx = tid & 15;
    float acc[4][4] = {};
#pragma unroll
    for (int kk = 0; kk < HD_; kk++) {
        float a[4], b[4];
#pragma unroll
        for (int i = 0; i < 4; i++) a[i] = Qs[kk][ty*4 + i];
#pragma unroll
        for (int j = 0; j < 4; j++) b[j] = Ks[kk][tx*4 + j];
#pragma unroll
        for (int i = 0; i < 4; i++)
#pragma unroll
            for (int j = 0; j < 4; j++)
                acc[i][j] += a[i] * b[j];
    }

    float* ab = attn + (size_t)bh * N_ * N_;
#pragma unroll
    for (int i = 0; i < 4; i++) {
        int qi = qt + ty*4 + i;
        if (qi >= N_) continue;
#pragma unroll
        for (int j = 0; j < 4; j++) {
            int kj = kt + tx*4 + j;
            if (kj < N_) ab[(size_t)qi * N_ + kj] = acc[i][j];
        }
    }
}

// ---------------- cls scores, exact top-k rank, mask + keep_mask ----------------
__global__ __launch_bounds__(256)
void topk_mask(const float* __restrict__ attn, float* __restrict__ keep_out,
               const int* __restrict__ num_keep)
{
    __shared__ float s[196];
    const int b = blockIdx.x;
    const int t = threadIdx.x;
    const int k = num_keep[0];

    if (t < 196) {
        float sum = 0.f;
        const float* base = attn + (size_t)b * H_ * N_ * N_ + (t + 1);
#pragma unroll
        for (int h = 0; h < H_; h++) sum += base[(size_t)h * N_ * N_];
        s[t] = sum * (1.0f / 12.0f);
    }
    __syncthreads();

    if (t < 196) {
        float mine = s[t];
        int rank = 0;
        for (int i = 0; i < 196; i++) {
            float si = s[i];
            rank += (si > mine) || (si == mine && i < t);
        }
        bool keep = rank < k;
        g_mask[b * N_ + t + 1]   = keep ? 0.f : MASK_NEG_;
        keep_out[b * N_ + t + 1] = keep ? 1.f : 0.f;
    }
    if (t == 0) {
        g_mask[b * N_]   = 0.f;
        keep_out[b * N_] = 1.f;
    }
}

// ---------------- masked softmax + attn @ V -> ctx[b,n,h,d] ----------------
__global__ __launch_bounds__(256)
void softmax_av(const float* __restrict__ attn)
{
    extern __shared__ float smemf[];
    float* Vs    = smemf;
    float* msk   = Vs + N_ * HD_;
    float* prows = msk + N_;

    const int bh = blockIdx.x;
    const int b  = bh / H_;
    const int h  = bh - b * H_;
    const int tid = threadIdx.x;

    const float* vb = g_v + (size_t)bh * N_ * HD_;
    for (int i = tid; i < (N_ * HD_) / 4; i += 256)
        reinterpret_cast<float4*>(Vs)[i] = reinterpret_cast<const float4*>(vb)[i];
    for (int i = tid; i < N_; i += 256) msk[i] = g_mask[b * N_ + i];
    __syncthreads();

    const int w = tid >> 5, lane = tid & 31;
    const float* ab = attn + (size_t)bh * N_ * N_;

    for (int base = w * 4; base < N_; base += 32) {
        float xv[4][7];
        float mx[4] = {-1e30f, -1e30f, -1e30f, -1e30f};
#pragma unroll
        for (int r = 0; r < 4; r++) {
            int row = base + r;
            if (row >= N_) continue;
            const float* arow = ab + (size_t)row * N_;
#pragma unroll
            for (int t = 0; t < 7; t++) {
                int j = lane + t * 32;
                float x = (j < N_) ? (arow[j] + msk[j]) : -1e30f;
                xv[r][t] = x;
                mx[r] = fmaxf(mx[r], x);
            }
        }
#pragma unroll
        for (int r = 0; r < 4; r++)
            for (int o = 16; o > 0; o >>= 1)
                mx[r] = fmaxf(mx[r], __shfl_xor_sync(0xffffffffu, mx[r], o));

        float sum[4] = {0.f, 0.f, 0.f, 0.f};
#pragma unroll
        for (int r = 0; r < 4; r++) {
            int row = base + r;
            if (row >= N_) continue;
            float* pr = prows + (w * 4 + r) * N_;
#pragma unroll
            for (int t = 0; t < 7; t++) {
                int j = lane + t * 32;
                if (j < N_) {
                    float e = __expf(xv[r][t] - mx[r]);
                    pr[j] = e;
                    sum[r] += e;
                }
            }
        }
#pragma unroll
        for (int r = 0; r < 4; r++)
            for (int o = 16; o > 0; o >>= 1)
                sum[r] += __shfl_xor_sync(0xffffffffu, sum[r], o);

        __syncwarp();

        float acc0[4] = {0.f,0.f,0.f,0.f}, acc1[4] = {0.f,0.f,0.f,0.f};
        const float* pr0 = prows + (w * 4 + 0) * N_;
        const float* pr1 = prows + (w * 4 + 1) * N_;
        const float* pr2 = prows + (w * 4 + 2) * N_;
        const float* pr3 = prows + (w * 4 + 3) * N_;
        for (int j = 0; j < N_; j++) {
            float v0 = Vs[j * HD_ + lane];
            float v1 = Vs[j * HD_ + lane + 32];
            float p0 = pr0[j], p1 = pr1[j], p2 = pr2[j], p3 = pr3[j];
            acc0[0] += p0 * v0; acc1[0] += p0 * v1;
            acc0[1] += p1 * v0; acc1[1] += p1 * v1;
            acc0[2] += p2 * v0; acc1[2] += p2 * v1;
            acc0[3] += p3 * v0; acc1[3] += p3 * v1;
        }
#pragma unroll
        for (int r = 0; r < 4; r++) {
            int row = base + r;
            if (row >= N_) continue;
            float inv = 1.f / sum[r];
            size_t o = ((size_t)(b * N_ + row) * H_ + h) * HD_;
            g_ctx[o + lane]      = acc0[r] * inv;
            g_ctx[o + lane + 32] = acc1[r] * inv;
        }
        __syncwarp();
    }
}

// ---------------- launch ----------------
extern "C" void kernel_launch(void* const* d_in, const int* in_sizes, int n_in,
                              void* d_out, int out_size)
{
    const float* x      = (const float*)d_in[0];
    const float* qkv_w  = (const float*)d_in[1];
    const float* qkv_b  = (const float*)d_in[2];
    const float* proj_w = (const float*)d_in[3];
    const float* proj_b = (const float*)d_in[4];
    const int*   nkeep  = (const int*)  d_in[5];

    float* out       = (float*)d_out;                       // [B,N,C]
    float* keep_mask = out + (size_t)MROWS * C_;            // [B,N,1]
    float* attn      = keep_mask + MROWS;                   // [B,H,N,N]

    const int SMEM4 = (N_ * HD_ + N_ + 32 * N_) * (int)sizeof(float);
    cudaFuncSetAttribute((const void*)softmax_av,
                         cudaFuncAttributeMaxDynamicSharedMemorySize, SMEM4);
    cudaFuncSetAttribute((const void*)gemm_mma<0>,
                         cudaFuncAttributeMaxDynamicSharedMemorySize, GEMM_SMEM_BYTES);
    cudaFuncSetAttribute((const void*)gemm_mma<1>,
                         cudaFuncAttributeMaxDynamicSharedMemorySize, GEMM_SMEM_BYTES);

    // 1) qkv GEMM (3xTF32 mma.sync) -> g_q (scaled), g_k, g_v
    gemm_mma<0><<<dim3((3 * C_) / 128, (MROWS + 127) / 128), 256, GEMM_SMEM_BYTES>>>(
        x, qkv_w, qkv_b, nullptr, MROWS, 3 * C_, C_);

    // 2) attn_rt = q @ k^T, written directly into output region
    attn_scores<<<dim3(4, 4, BH_), 256>>>(attn);

    // 3) cls mean + top-k -> additive mask + keep_mask output
    topk_mask<<<B_, 256>>>(attn, keep_mask, nkeep);

    // 4) masked softmax + attn @ V -> g_ctx [b,n,h,d]
    softmax_av<<<BH_, 256, SMEM4>>>(attn);

    // 5) proj GEMM (3xTF32 mma.sync) -> out
    gemm_mma<1><<<dim3(C_ / 128, (MROWS + 127) / 128), 256, GEMM_SMEM_BYTES>>>(
        nullptr, proj_w, proj_b, out, MROWS, C_, C_);
}

// round 5
// speedup vs baseline: 1.9922x; 1.7169x over previous
#include <cuda_runtime.h>
#include <cuda_fp16.h>
#include <cstdint>
#include <math.h>

#define B_   64
#define N_   197
#define C_   768
#define H_   12
#define HD_  64
#define BH_  (B_*H_)            // 768
#define MROWS (B_*N_)           // 12608
#define MASK_NEG_ -100000.0f

// ---------------- scratch ----------------
__device__ __align__(16) float g_q[(size_t)BH_*N_*HD_];   // scaled q, [b,h,n,d]
__device__ __align__(16) float g_k[(size_t)BH_*N_*HD_];
__device__ __align__(16) float g_v[(size_t)BH_*N_*HD_];
__device__ __align__(16) float g_ctx[(size_t)MROWS*C_];   // [b,n,h,d] == [m, C]
__device__ float g_mask[B_*N_];                           // additive mask

// ================= fp16 mma helpers =================
__device__ __forceinline__ void mma_f16(float acc[4], const uint32_t a[4], const uint32_t b[2]) {
    asm volatile("mma.sync.aligned.m16n8k16.row.col.f32.f16.f16.f32 "
        "{%0,%1,%2,%3}, {%4,%5,%6,%7}, {%8,%9}, {%0,%1,%2,%3};"
        : "+f"(acc[0]), "+f"(acc[1]), "+f"(acc[2]), "+f"(acc[3])
        : "r"(a[0]), "r"(a[1]), "r"(a[2]), "r"(a[3]), "r"(b[0]), "r"(b[1]));
}

__device__ __forceinline__ uint32_t pack_hi(float x, float y, float& lx, float& ly) {
    __half hx = __float2half_rn(x), hy = __float2half_rn(y);
    lx = x - __half2float(hx);
    ly = y - __half2float(hy);
    __half2 h = __halves2half2(hx, hy);
    return *reinterpret_cast<uint32_t*>(&h);
}
__device__ __forceinline__ uint32_t pack_lo(float lx, float ly) {
    __half2 h = __halves2half2(__float2half_rn(lx), __float2half_rn(ly));
    return *reinterpret_cast<uint32_t*>(&h);
}

// ---- smem layout (uint32 units after bias) ----
// bias[128 floats] | stage0: Ah[2048] Al[2048] Bh[2048] Bl[2048] | stage1: same
#define STAGE_U32 (4*2048)
#define GEMM_SMEM_BYTES (128*4 + 2*STAGE_U32*4)   // 66048

// fragment-layout indexers
#define A_IDX(kc, mt, lane, reg) ((((kc)*8  + (mt))*32 + (lane))*4 + (reg))
#define B_IDX(kc, nt, lane, reg) ((((kc)*16 + (nt))*32 + (lane))*2 + (reg))

// ================= fp16-split (Markidis) mma.sync GEMM =================
// out[M,N] = A[M,K] @ W[N,K]^T + bias.  MODE 0: A=x, scatter q/k/v. MODE 1: A=g_ctx -> out.
template<int MODE>
__global__ __launch_bounds__(256, 2)
void gemm_mma(const float* __restrict__ A_in, const float* __restrict__ W,
              const float* __restrict__ bias, float* __restrict__ out,
              int M, int N, int K)
{
    const float* A = (MODE == 1) ? g_ctx : A_in;
    extern __shared__ float sm[];
    float*    s_bias = sm;
    uint32_t* sbase  = reinterpret_cast<uint32_t*>(sm + 128);

    const int tid   = threadIdx.x;
    const int lane  = tid & 31;
    const int wid   = tid >> 5;
    const int warp_m = wid & 1;     // 0..1  -> 64 rows
    const int warp_n = wid >> 1;    // 0..3  -> 32 cols
    const int bm = blockIdx.y * 128, bn = blockIdx.x * 128;

    if (tid < 128) s_bias[tid] = bias[bn + tid];

    float acc[4][4][4];
#pragma unroll
    for (int i = 0; i < 4; i++)
#pragma unroll
        for (int j = 0; j < 4; j++)
#pragma unroll
            for (int r = 0; r < 4; r++) acc[i][j][r] = 0.f;

    // ---- loader: split A and B into fragment-layout fp16 hi/lo ----
    auto load_stage = [&](uint32_t* st, int k0) {
        uint32_t* dAh = st;
        uint32_t* dAl = st + 2048;
        uint32_t* dBh = st + 4096;
        uint32_t* dBl = st + 6144;
#pragma unroll
        for (int it = 0; it < 4; it++) {
            int linear = tid + it * 256;         // 0..1023
            int row = linear >> 3;               // 0..127
            int c0  = (linear & 7) << 2;         // 0..28 step 4
            int kc  = c0 >> 4;                   // k16 chunk
            int kin = c0 & 15;

            // ---- A ----
            {
                int gm = bm + row;
                float4 v = make_float4(0.f, 0.f, 0.f, 0.f);
                if (gm < M) v = *reinterpret_cast<const float4*>(A + (size_t)gm * K + k0 + c0);
                int mt = row >> 4, rr = row & 15, gr = rr & 7;
                int reg  = (rr >> 3) + ((kin >= 8) ? 2 : 0);
                int ln0  = gr * 4 + ((kin & 7) >> 1);
                float lx, ly, lz, lw;
                uint32_t h01 = pack_hi(v.x, v.y, lx, ly);
                uint32_t h23 = pack_hi(v.z, v.w, lz, lw);
                dAh[A_IDX(kc, mt, ln0,     reg)] = h01;
                dAh[A_IDX(kc, mt, ln0 + 1, reg)] = h23;
                dAl[A_IDX(kc, mt, ln0,     reg)] = pack_lo(lx, ly);
                dAl[A_IDX(kc, mt, ln0 + 1, reg)] = pack_lo(lz, lw);
            }
            // ---- B ----
            {
                float4 v = *reinterpret_cast<const float4*>(W + (size_t)(bn + row) * K + k0 + c0);
                int nt = row >> 3, nc = row & 7;
                int reg = (kin >= 8) ? 1 : 0;
                int ln0 = nc * 4 + ((kin & 7) >> 1);
                float lx, ly, lz, lw;
                uint32_t h01 = pack_hi(v.x, v.y, lx, ly);
                uint32_t h23 = pack_hi(v.z, v.w, lz, lw);
                dBh[B_IDX(kc, nt, ln0,     reg)] = h01;
                dBh[B_IDX(kc, nt, ln0 + 1, reg)] = h23;
                dBl[B_IDX(kc, nt, ln0,     reg)] = pack_lo(lx, ly);
                dBl[B_IDX(kc, nt, ln0 + 1, reg)] = pack_lo(lz, lw);
            }
        }
    };

    auto compute_stage = [&](const uint32_t* st) {
        const uint32_t* cAh = st;
        const uint32_t* cAl = st + 2048;
        const uint32_t* cBh = st + 4096;
        const uint32_t* cBl = st + 6144;
#pragma unroll
        for (int kc = 0; kc < 2; kc++) {
            uint32_t ah[4][4], al[4][4];
#pragma unroll
            for (int im = 0; im < 4; im++) {
                int mt = warp_m * 4 + im;
                uint4 h = *reinterpret_cast<const uint4*>(&cAh[A_IDX(kc, mt, lane, 0)]);
                uint4 l = *reinterpret_cast<const uint4*>(&cAl[A_IDX(kc, mt, lane, 0)]);
                ah[im][0] = h.x; ah[im][1] = h.y; ah[im][2] = h.z; ah[im][3] = h.w;
                al[im][0] = l.x; al[im][1] = l.y; al[im][2] = l.z; al[im][3] = l.w;
            }
#pragma unroll
            for (int jn = 0; jn < 4; jn++) {
                int nt = warp_n * 4 + jn;
                uint2 h = *reinterpret_cast<const uint2*>(&cBh[B_IDX(kc, nt, lane, 0)]);
                uint2 l = *reinterpret_cast<const uint2*>(&cBl[B_IDX(kc, nt, lane, 0)]);
                uint32_t bh[2] = { h.x, h.y };
                uint32_t bl[2] = { l.x, l.y };
#pragma unroll
                for (int im = 0; im < 4; im++) {
                    mma_f16(acc[im][jn], al[im], bh);
                    mma_f16(acc[im][jn], ah[im], bl);
                    mma_f16(acc[im][jn], ah[im], bh);
                }
            }
        }
    };

    uint32_t* st0 = sbase;
    uint32_t* st1 = sbase + STAGE_U32;

    load_stage(st0, 0);
    __syncthreads();

    const int nchunk = K >> 5;   // 24
    for (int c = 0; c < nchunk; c++) {
        uint32_t* cur = (c & 1) ? st1 : st0;
        uint32_t* nxt = (c & 1) ? st0 : st1;
        if (c + 1 < nchunk) load_stage(nxt, (c + 1) << 5);
        compute_stage(cur);
        __syncthreads();
    }

    // ---- epilogue ----
#pragma unroll
    for (int im = 0; im < 4; im++) {
        int row0 = warp_m * 64 + im * 16 + (lane >> 2);
#pragma unroll
        for (int jn = 0; jn < 4; jn++) {
            int col0 = warp_n * 32 + jn * 8 + (lane & 3) * 2;
#pragma unroll
            for (int r = 0; r < 4; r++) {
                int m  = bm + row0 + ((r >= 2) ? 8 : 0);
                int cl = col0 + (r & 1);
                if (m >= M) continue;
                int cc = bn + cl;
                float val = acc[im][jn][r] + s_bias[cl];
                if (MODE == 0) {
                    int bb = m / N_;
                    int nn2 = m - bb * N_;
                    int part = cc / C_;
                    int rem  = cc - part * C_;
                    int h = rem >> 6;
                    int dd = rem & 63;
                    size_t idx = ((size_t)(bb * H_ + h) * N_ + nn2) * HD_ + dd;
                    if      (part == 0) g_q[idx] = val * 0.125f;
                    else if (part == 1) g_k[idx] = val;
                    else                g_v[idx] = val;
                } else {
                    out[(size_t)m * N + cc] = val;
                }
            }
        }
    }
}

// ---------------- attn_rt = q @ k^T (q pre-scaled), per (b,h) 197x197 ----------------
__global__ __launch_bounds__(256)
void attn_scores(float* __restrict__ attn)
{
    __shared__ float Qs[HD_][65];
    __shared__ float Ks[HD_][65];

    const int bh = blockIdx.z;
    const int qt = blockIdx.y * 64;
    const int kt = blockIdx.x * 64;
    const int tid = threadIdx.x;

    const float* qb = g_q + (size_t)bh * N_ * HD_;
    const float* kb = g_k + (size_t)bh * N_ * HD_;

    const int lr = tid >> 4;
    const int lc = (tid & 15) << 2;

#pragma unroll
    for (int s = 0; s < 4; s++) {
        int row = lr + s * 16;
        float4 v;
        int gq = qt + row;
        if (gq < N_) v = *reinterpret_cast<const float4*>(qb + (size_t)gq * HD_ + lc);
        else         v = make_float4(0.f, 0.f, 0.f, 0.f);
        Qs[lc+0][row] = v.x; Qs[lc+1][row] = v.y;
        Qs[lc+2][row] = v.z; Qs[lc+3][row] = v.w;

        int gk = kt + row;
        if (gk < N_) v = *reinterpret_cast<const float4*>(kb + (size_t)gk * HD_ + lc);
        else         v = make_float4(0.f, 0.f, 0.f, 0.f);
        Ks[lc+0][row] = v.x; Ks[lc+1][row] = v.y;
        Ks[lc+2][row] = v.z; Ks[lc+3][row] = v.w;
    }
    __syncthreads();

    const int ty = tid >> 4, tx = tid & 15;
    float acc[4][4] = {};
#pragma unroll
    for (int kk = 0; kk < HD_; kk++) {
        float a[4], b[4];
#pragma unroll
        for (int i = 0; i < 4; i++) a[i] = Qs[kk][ty*4 + i];
#pragma unroll
        for (int j = 0; j < 4; j++) b[j] = Ks[kk][tx*4 + j];
#pragma unroll
        for (int i = 0; i < 4; i++)
#pragma unroll
            for (int j = 0; j < 4; j++)
                acc[i][j] += a[i] * b[j];
    }

    float* ab = attn + (size_t)bh * N_ * N_;
#pragma unroll
    for (int i = 0; i < 4; i++) {
        int qi = qt + ty*4 + i;
        if (qi >= N_) continue;
#pragma unroll
        for (int j = 0; j < 4; j++) {
            int kj = kt + tx*4 + j;
            if (kj < N_) ab[(size_t)qi * N_ + kj] = acc[i][j];
        }
    }
}

// ---------------- cls scores, exact top-k rank, mask + keep_mask ----------------
__global__ __launch_bounds__(256)
void topk_mask(const float* __restrict__ attn, float* __restrict__ keep_out,
               const int* __restrict__ num_keep)
{
    __shared__ float s[196];
    const int b = blockIdx.x;
    const int t = threadIdx.x;
    const int k = num_keep[0];

    if (t < 196) {
        float sum = 0.f;
        const float* base = attn + (size_t)b * H_ * N_ * N_ + (t + 1);
#pragma unroll
        for (int h = 0; h < H_; h++) sum += base[(size_t)h * N_ * N_];
        s[t] = sum * (1.0f / 12.0f);
    }
    __syncthreads();

    if (t < 196) {
        float mine = s[t];
        int rank = 0;
        for (int i = 0; i < 196; i++) {
            float si = s[i];
            rank += (si > mine) || (si == mine && i < t);
        }
        bool keep = rank < k;
        g_mask[b * N_ + t + 1]   = keep ? 0.f : MASK_NEG_;
        keep_out[b * N_ + t + 1] = keep ? 1.f : 0.f;
    }
    if (t == 0) {
        g_mask[b * N_]   = 0.f;
        keep_out[b * N_] = 1.f;
    }
}

// ---------------- masked softmax + attn @ V -> ctx[b,n,h,d] ----------------
__global__ __launch_bounds__(256)
void softmax_av(const float* __restrict__ attn)
{
    extern __shared__ float smemf[];
    float* Vs    = smemf;
    float* msk   = Vs + N_ * HD_;
    float* prows = msk + N_;

    const int bh = blockIdx.x;
    const int b  = bh / H_;
    const int h  = bh - b * H_;
    const int tid = threadIdx.x;

    const float* vb = g_v + (size_t)bh * N_ * HD_;
    for (int i = tid; i < (N_ * HD_) / 4; i += 256)
        reinterpret_cast<float4*>(Vs)[i] = reinterpret_cast<const float4*>(vb)[i];
    for (int i = tid; i < N_; i += 256) msk[i] = g_mask[b * N_ + i];
    __syncthreads();

    const int w = tid >> 5, lane = tid & 31;
    const float* ab = attn + (size_t)bh * N_ * N_;

    for (int base = w * 4; base < N_; base += 32) {
        float xv[4][7];
        float mx[4] = {-1e30f, -1e30f, -1e30f, -1e30f};
#pragma unroll
        for (int r = 0; r < 4; r++) {
            int row = base + r;
            if (row >= N_) continue;
            const float* arow = ab + (size_t)row * N_;
#pragma unroll
            for (int t = 0; t < 7; t++) {
                int j = lane + t * 32;
                float x = (j < N_) ? (arow[j] + msk[j]) : -1e30f;
                xv[r][t] = x;
                mx[r] = fmaxf(mx[r], x);
            }
        }
#pragma unroll
        for (int r = 0; r < 4; r++)
            for (int o = 16; o > 0; o >>= 1)
                mx[r] = fmaxf(mx[r], __shfl_xor_sync(0xffffffffu, mx[r], o));

        float sum[4] = {0.f, 0.f, 0.f, 0.f};
#pragma unroll
        for (int r = 0; r < 4; r++) {
            int row = base + r;
            if (row >= N_) continue;
            float* pr = prows + (w * 4 + r) * N_;
#pragma unroll
            for (int t = 0; t < 7; t++) {
                int j = lane + t * 32;
                if (j < N_) {
                    float e = __expf(xv[r][t] - mx[r]);
                    pr[j] = e;
                    sum[r] += e;
                }
            }
        }
#pragma unroll
        for (int r = 0; r < 4; r++)
            for (int o = 16; o > 0; o >>= 1)
                sum[r] += __shfl_xor_sync(0xffffffffu, sum[r], o);

        __syncwarp();

        float acc0[4] = {0.f,0.f,0.f,0.f}, acc1[4] = {0.f,0.f,0.f,0.f};
        const float* pr0 = prows + (w * 4 + 0) * N_;
        const float* pr1 = prows + (w * 4 + 1) * N_;
        const float* pr2 = prows + (w * 4 + 2) * N_;
        const float* pr3 = prows + (w * 4 + 3) * N_;
        for (int j = 0; j < N_; j++) {
            float v0 = Vs[j * HD_ + lane];
            float v1 = Vs[j * HD_ + lane + 32];
            float p0 = pr0[j], p1 = pr1[j], p2 = pr2[j], p3 = pr3[j];
            acc0[0] += p0 * v0; acc1[0] += p0 * v1;
            acc0[1] += p1 * v0; acc1[1] += p1 * v1;
            acc0[2] += p2 * v0; acc1[2] += p2 * v1;
            acc0[3] += p3 * v0; acc1[3] += p3 * v1;
        }
#pragma unroll
        for (int r = 0; r < 4; r++) {
            int row = base + r;
            if (row >= N_) continue;
            float inv = 1.f / sum[r];
            size_t o = ((size_t)(b * N_ + row) * H_ + h) * HD_;
            g_ctx[o + lane]      = acc0[r] * inv;
            g_ctx[o + lane + 32] = acc1[r] * inv;
        }
        __syncwarp();
    }
}

// ---------------- launch ----------------
extern "C" void kernel_launch(void* const* d_in, const int* in_sizes, int n_in,
                              void* d_out, int out_size)
{
    const float* x      = (const float*)d_in[0];
    const float* qkv_w  = (const float*)d_in[1];
    const float* qkv_b  = (const float*)d_in[2];
    const float* proj_w = (const float*)d_in[3];
    const float* proj_b = (const float*)d_in[4];
    const int*   nkeep  = (const int*)  d_in[5];

    float* out       = (float*)d_out;                       // [B,N,C]
    float* keep_mask = out + (size_t)MROWS * C_;            // [B,N,1]
    float* attn      = keep_mask + MROWS;                   // [B,H,N,N]

    const int SMEM4 = (N_ * HD_ + N_ + 32 * N_) * (int)sizeof(float);
    cudaFuncSetAttribute((const void*)softmax_av,
                         cudaFuncAttributeMaxDynamicSharedMemorySize, SMEM4);
    cudaFuncSetAttribute((const void*)gemm_mma<0>,
                         cudaFuncAttributeMaxDynamicSharedMemorySize, GEMM_SMEM_BYTES);
    cudaFuncSetAttribute((const void*)gemm_mma<1>,
                         cudaFuncAttributeMaxDynamicSharedMemorySize, GEMM_SMEM_BYTES);

    // 1) qkv GEMM (fp16-split mma.sync m16n8k16) -> g_q (scaled), g_k, g_v
    gemm_mma<0><<<dim3((3 * C_) / 128, (MROWS + 127) / 128), 256, GEMM_SMEM_BYTES>>>(
        x, qkv_w, qkv_b, nullptr, MROWS, 3 * C_, C_);

    // 2) attn_rt = q @ k^T, written directly into output region
    attn_scores<<<dim3(4, 4, BH_), 256>>>(attn);

    // 3) cls mean + top-k -> additive mask + keep_mask output
    topk_mask<<<B_, 256>>>(attn, keep_mask, nkeep);

    // 4) masked softmax + attn @ V -> g_ctx [b,n,h,d]
    softmax_av<<<BH_, 256, SMEM4>>>(attn);

    // 5) proj GEMM (fp16-split mma.sync m16n8k16) -> out
    gemm_mma<1><<<dim3(C_ / 128, (MROWS + 127) / 128), 256, GEMM_SMEM_BYTES>>>(
        nullptr, proj_w, proj_b, out, MROWS, C_, C_);
}

// round 6
// speedup vs baseline: 2.0852x; 1.0467x over previous
#include <cuda_runtime.h>
#include <cuda_fp16.h>
#include <cstdint>
#include <math.h>

#define B_   64
#define N_   197
#define C_   768
#define H_   12
#define HD_  64
#define BH_  (B_*H_)            // 768
#define MROWS (B_*N_)           // 12608
#define MASK_NEG_ -100000.0f
#define LOG2E_ 1.4426950408889634f

// ---------------- scratch ----------------
__device__ __align__(16) float g_q[(size_t)BH_*N_*HD_];   // scaled q, [b,h,n,d]
__device__ __align__(16) float g_k[(size_t)BH_*N_*HD_];
__device__ __align__(16) float g_v[(size_t)BH_*N_*HD_];
__device__ __align__(16) float g_ctx[(size_t)MROWS*C_];   // [b,n,h,d] == [m, C]
__device__ float g_mask[B_*N_];                           // additive mask

// ================= fp16 mma helpers =================
__device__ __forceinline__ void mma_f16(float acc[4], const uint32_t a[4], const uint32_t b[2]) {
    asm volatile("mma.sync.aligned.m16n8k16.row.col.f32.f16.f16.f32 "
        "{%0,%1,%2,%3}, {%4,%5,%6,%7}, {%8,%9}, {%0,%1,%2,%3};"
        : "+f"(acc[0]), "+f"(acc[1]), "+f"(acc[2]), "+f"(acc[3])
        : "r"(a[0]), "r"(a[1]), "r"(a[2]), "r"(a[3]), "r"(b[0]), "r"(b[1]));
}

__device__ __forceinline__ uint32_t pack_hi(float x, float y, float& lx, float& ly) {
    __half hx = __float2half_rn(x), hy = __float2half_rn(y);
    lx = x - __half2float(hx);
    ly = y - __half2float(hy);
    __half2 h = __halves2half2(hx, hy);
    return *reinterpret_cast<uint32_t*>(&h);
}
__device__ __forceinline__ uint32_t pack_lo(float lx, float ly) {
    __half2 h = __halves2half2(__float2half_rn(lx), __float2half_rn(ly));
    return *reinterpret_cast<uint32_t*>(&h);
}

__device__ __forceinline__ uint32_t ex2_f16x2(float t0, float t1) {
    __half2 h = __floats2half2_rn(t0, t1);
    uint32_t in = *reinterpret_cast<uint32_t*>(&h), out;
    asm("ex2.approx.f16x2 %0, %1;" : "=r"(out) : "r"(in));
    return out;
}

// ---- gemm smem layout (uint32 units after bias) ----
#define STAGE_U32 (4*2048)
#define GEMM_SMEM_BYTES (128*4 + 2*STAGE_U32*4)   // 66048

// fragment-layout indexers (gemm)
#define A_IDX(kc, mt, lane, reg) ((((kc)*8  + (mt))*32 + (lane))*4 + (reg))
#define B_IDX(kc, nt, lane, reg) ((((kc)*16 + (nt))*32 + (lane))*2 + (reg))

// ================= fp16-split (Markidis) mma.sync GEMM =================
template<int MODE>
__global__ __launch_bounds__(256, 2)
void gemm_mma(const float* __restrict__ A_in, const float* __restrict__ W,
              const float* __restrict__ bias, float* __restrict__ out,
              int M, int N, int K)
{
    const float* A = (MODE == 1) ? g_ctx : A_in;
    extern __shared__ float sm[];
    float*    s_bias = sm;
    uint32_t* sbase  = reinterpret_cast<uint32_t*>(sm + 128);

    const int tid   = threadIdx.x;
    const int lane  = tid & 31;
    const int wid   = tid >> 5;
    const int warp_m = wid & 1;
    const int warp_n = wid >> 1;
    const int bm = blockIdx.y * 128, bn = blockIdx.x * 128;

    if (tid < 128) s_bias[tid] = bias[bn + tid];

    float acc[4][4][4];
#pragma unroll
    for (int i = 0; i < 4; i++)
#pragma unroll
        for (int j = 0; j < 4; j++)
#pragma unroll
            for (int r = 0; r < 4; r++) acc[i][j][r] = 0.f;

    auto load_stage = [&](uint32_t* st, int k0) {
        uint32_t* dAh = st;
        uint32_t* dAl = st + 2048;
        uint32_t* dBh = st + 4096;
        uint32_t* dBl = st + 6144;
#pragma unroll
        for (int it = 0; it < 4; it++) {
            int linear = tid + it * 256;
            int row = linear >> 3;
            int c0  = (linear & 7) << 2;
            int kc  = c0 >> 4;
            int kin = c0 & 15;
            {
                int gm = bm + row;
                float4 v = make_float4(0.f, 0.f, 0.f, 0.f);
                if (gm < M) v = *reinterpret_cast<const float4*>(A + (size_t)gm * K + k0 + c0);
                int mt = row >> 4, rr = row & 15, gr = rr & 7;
                int reg  = (rr >> 3) + ((kin >= 8) ? 2 : 0);
                int ln0  = gr * 4 + ((kin & 7) >> 1);
                float lx, ly, lz, lw;
                uint32_t h01 = pack_hi(v.x, v.y, lx, ly);
                uint32_t h23 = pack_hi(v.z, v.w, lz, lw);
                dAh[A_IDX(kc, mt, ln0,     reg)] = h01;
                dAh[A_IDX(kc, mt, ln0 + 1, reg)] = h23;
                dAl[A_IDX(kc, mt, ln0,     reg)] = pack_lo(lx, ly);
                dAl[A_IDX(kc, mt, ln0 + 1, reg)] = pack_lo(lz, lw);
            }
            {
                float4 v = *reinterpret_cast<const float4*>(W + (size_t)(bn + row) * K + k0 + c0);
                int nt = row >> 3, nc = row & 7;
                int reg = (kin >= 8) ? 1 : 0;
                int ln0 = nc * 4 + ((kin & 7) >> 1);
                float lx, ly, lz, lw;
                uint32_t h01 = pack_hi(v.x, v.y, lx, ly);
                uint32_t h23 = pack_hi(v.z, v.w, lz, lw);
                dBh[B_IDX(kc, nt, ln0,     reg)] = h01;
                dBh[B_IDX(kc, nt, ln0 + 1, reg)] = h23;
                dBl[B_IDX(kc, nt, ln0,     reg)] = pack_lo(lx, ly);
                dBl[B_IDX(kc, nt, ln0 + 1, reg)] = pack_lo(lz, lw);
            }
        }
    };

    auto compute_stage = [&](const uint32_t* st) {
        const uint32_t* cAh = st;
        const uint32_t* cAl = st + 2048;
        const uint32_t* cBh = st + 4096;
        const uint32_t* cBl = st + 6144;
#pragma unroll
        for (int kc = 0; kc < 2; kc++) {
            uint32_t ah[4][4], al[4][4];
#pragma unroll
            for (int im = 0; im < 4; im++) {
                int mt = warp_m * 4 + im;
                uint4 h = *reinterpret_cast<const uint4*>(&cAh[A_IDX(kc, mt, lane, 0)]);
                uint4 l = *reinterpret_cast<const uint4*>(&cAl[A_IDX(kc, mt, lane, 0)]);
                ah[im][0] = h.x; ah[im][1] = h.y; ah[im][2] = h.z; ah[im][3] = h.w;
                al[im][0] = l.x; al[im][1] = l.y; al[im][2] = l.z; al[im][3] = l.w;
            }
#pragma unroll
            for (int jn = 0; jn < 4; jn++) {
                int nt = warp_n * 4 + jn;
                uint2 h = *reinterpret_cast<const uint2*>(&cBh[B_IDX(kc, nt, lane, 0)]);
                uint2 l = *reinterpret_cast<const uint2*>(&cBl[B_IDX(kc, nt, lane, 0)]);
                uint32_t bh[2] = { h.x, h.y };
                uint32_t bl[2] = { l.x, l.y };
#pragma unroll
                for (int im = 0; im < 4; im++) {
                    mma_f16(acc[im][jn], al[im], bh);
                    mma_f16(acc[im][jn], ah[im], bl);
                    mma_f16(acc[im][jn], ah[im], bh);
                }
            }
        }
    };

    uint32_t* st0 = sbase;
    uint32_t* st1 = sbase + STAGE_U32;

    load_stage(st0, 0);
    __syncthreads();

    const int nchunk = K >> 5;
    for (int c = 0; c < nchunk; c++) {
        uint32_t* cur = (c & 1) ? st1 : st0;
        uint32_t* nxt = (c & 1) ? st0 : st1;
        if (c + 1 < nchunk) load_stage(nxt, (c + 1) << 5);
        compute_stage(cur);
        __syncthreads();
    }

#pragma unroll
    for (int im = 0; im < 4; im++) {
        int row0 = warp_m * 64 + im * 16 + (lane >> 2);
#pragma unroll
        for (int jn = 0; jn < 4; jn++) {
            int col0 = warp_n * 32 + jn * 8 + (lane & 3) * 2;
#pragma unroll
            for (int r = 0; r < 4; r++) {
                int m  = bm + row0 + ((r >= 2) ? 8 : 0);
                int cl = col0 + (r & 1);
                if (m >= M) continue;
                int cc = bn + cl;
                float val = acc[im][jn][r] + s_bias[cl];
                if (MODE == 0) {
                    int bb = m / N_;
                    int nn2 = m - bb * N_;
                    int part = cc / C_;
                    int rem  = cc - part * C_;
                    int h = rem >> 6;
                    int dd = rem & 63;
                    size_t idx = ((size_t)(bb * H_ + h) * N_ + nn2) * HD_ + dd;
                    if      (part == 0) g_q[idx] = val * 0.125f;
                    else if (part == 1) g_k[idx] = val;
                    else                g_v[idx] = val;
                } else {
                    out[(size_t)m * N + cc] = val;
                }
            }
        }
    }
}

// ================= attn_rt = q @ k^T via fp16-split mma =================
// grid (2, BH_): qt in {0,1} covers 128 q-rows; per block: 128 x 208 scores.
// Q frag [4kc][8mt][32][4] hi/lo ; K frag [4kc][26nt][32][2] hi/lo
#define QA_H 0
#define QA_L 4096
#define KB_H 8192
#define KB_L 14848
#define ATTN_SMEM_U32 21504
#define ATTN_SMEM_BYTES (ATTN_SMEM_U32*4)   // 86016

__global__ __launch_bounds__(256)
void attn_scores_mma(float* __restrict__ attn)
{
    extern __shared__ uint32_t smu[];
    const int tid = threadIdx.x;
    const int lane = tid & 31;
    const int wid = tid >> 5;
    const int qt = blockIdx.x;
    const int bh = blockIdx.y;

    const float* qb = g_q + (size_t)bh * N_ * HD_;
    const float* kb = g_k + (size_t)bh * N_ * HD_;

    // load Q rows (qt*128 .. +127) into A-fragment hi/lo
    for (int idx = tid; idx < 2048; idx += 256) {
        int row = idx >> 4, g = idx & 15;
        int kc = g >> 2, kin = (g & 3) << 2;
        int gr0 = qt * 128 + row;
        float4 v = make_float4(0.f, 0.f, 0.f, 0.f);
        if (gr0 < N_) v = *reinterpret_cast<const float4*>(qb + (size_t)gr0 * HD_ + kc * 16 + kin);
        int mt = row >> 4, rr = row & 15, gr = rr & 7;
        int reg = (rr >> 3) + ((kin >= 8) ? 2 : 0);
        int ln0 = gr * 4 + ((kin & 7) >> 1);
        float lx, ly, lz, lw;
        uint32_t h01 = pack_hi(v.x, v.y, lx, ly);
        uint32_t h23 = pack_hi(v.z, v.w, lz, lw);
        smu[QA_H + ((kc*8 + mt)*32 + ln0    )*4 + reg] = h01;
        smu[QA_H + ((kc*8 + mt)*32 + ln0 + 1)*4 + reg] = h23;
        smu[QA_L + ((kc*8 + mt)*32 + ln0    )*4 + reg] = pack_lo(lx, ly);
        smu[QA_L + ((kc*8 + mt)*32 + ln0 + 1)*4 + reg] = pack_lo(lz, lw);
    }
    // load K rows (0..207) into B-fragment hi/lo
    for (int idx = tid; idx < 3328; idx += 256) {
        int row = idx >> 4, g = idx & 15;
        int kc = g >> 2, kin = (g & 3) << 2;
        float4 v = make_float4(0.f, 0.f, 0.f, 0.f);
        if (row < N_) v = *reinterpret_cast<const float4*>(kb + (size_t)row * HD_ + kc * 16 + kin);
        int nt = row >> 3, nc = row & 7;
        int reg = (kin >= 8) ? 1 : 0;
        int ln0 = nc * 4 + ((kin & 7) >> 1);
        float lx, ly, lz, lw;
        uint32_t h01 = pack_hi(v.x, v.y, lx, ly);
        uint32_t h23 = pack_hi(v.z, v.w, lz, lw);
        smu[KB_H + ((kc*26 + nt)*32 + ln0    )*2 + reg] = h01;
        smu[KB_H + ((kc*26 + nt)*32 + ln0 + 1)*2 + reg] = h23;
        smu[KB_L + ((kc*26 + nt)*32 + ln0    )*2 + reg] = pack_lo(lx, ly);
        smu[KB_L + ((kc*26 + nt)*32 + ln0 + 1)*2 + reg] = pack_lo(lz, lw);
    }
    __syncthreads();

    const int mt = wid;   // one m16 tile per warp
    float acc[26][4];
#pragma unroll
    for (int nt = 0; nt < 26; nt++)
#pragma unroll
        for (int r = 0; r < 4; r++) acc[nt][r] = 0.f;

#pragma unroll
    for (int kc = 0; kc < 4; kc++) {
        uint4 h4 = *reinterpret_cast<const uint4*>(&smu[QA_H + ((kc*8 + mt)*32 + lane)*4]);
        uint4 l4 = *reinterpret_cast<const uint4*>(&smu[QA_L + ((kc*8 + mt)*32 + lane)*4]);
        uint32_t ah[4] = { h4.x, h4.y, h4.z, h4.w };
        uint32_t al[4] = { l4.x, l4.y, l4.z, l4.w };
#pragma unroll
        for (int nt = 0; nt < 26; nt++) {
            uint2 bh2 = *reinterpret_cast<const uint2*>(&smu[KB_H + ((kc*26 + nt)*32 + lane)*2]);
            uint2 bl2 = *reinterpret_cast<const uint2*>(&smu[KB_L + ((kc*26 + nt)*32 + lane)*2]);
            uint32_t bh[2] = { bh2.x, bh2.y };
            uint32_t bl[2] = { bl2.x, bl2.y };
            mma_f16(acc[nt], al, bh);
            mma_f16(acc[nt], ah, bl);
            mma_f16(acc[nt], ah, bh);
        }
    }

    float* ab = attn + (size_t)bh * N_ * N_;
    int r0 = qt * 128 + mt * 16 + (lane >> 2);
#pragma unroll
    for (int nt = 0; nt < 26; nt++) {
        int c0 = nt * 8 + (lane & 3) * 2;
#pragma unroll
        for (int r = 0; r < 4; r++) {
            int row = r0 + ((r >= 2) ? 8 : 0);
            int col = c0 + (r & 1);
            if (row < N_ && col < N_) ab[(size_t)row * N_ + col] = acc[nt][r];
        }
    }
}

// ---------------- cls scores, exact top-k rank, mask + keep_mask ----------------
__global__ __launch_bounds__(256)
void topk_mask(const float* __restrict__ attn, float* __restrict__ keep_out,
               const int* __restrict__ num_keep)
{
    __shared__ float s[196];
    const int b = blockIdx.x;
    const int t = threadIdx.x;
    const int k = num_keep[0];

    if (t < 196) {
        float sum = 0.f;
        const float* base = attn + (size_t)b * H_ * N_ * N_ + (t + 1);
#pragma unroll
        for (int h = 0; h < H_; h++) sum += base[(size_t)h * N_ * N_];
        s[t] = sum * (1.0f / 12.0f);
    }
    __syncthreads();

    if (t < 196) {
        float mine = s[t];
        int rank = 0;
        for (int i = 0; i < 196; i++) {
            float si = s[i];
            rank += (si > mine) || (si == mine && i < t);
        }
        bool keep = rank < k;
        g_mask[b * N_ + t + 1]   = keep ? 0.f : MASK_NEG_;
        keep_out[b * N_ + t + 1] = keep ? 1.f : 0.f;
    }
    if (t == 0) {
        g_mask[b * N_]   = 0.f;
        keep_out[b * N_] = 1.f;
    }
}

// ---------------- masked softmax (fp16x2 exp) + attn @ V -> ctx ----------------
// dyn smem: Vs[197*64] f32 | msk[200] f32 | pr4[8 warps][200] uint2
#define SMAX_PR_OFF (N_ * HD_ + 200)                         // float offset of pr region
#define SMAX_SMEM_BYTES ((N_ * HD_ + 200) * 4 + 8 * 200 * 8) // 64032
__global__ __launch_bounds__(256)
void softmax_av(const float* __restrict__ attn)
{
    extern __shared__ float smemf[];
    float* Vs  = smemf;
    float* msk = Vs + N_ * HD_;
    uint2* pr  = reinterpret_cast<uint2*>(smemf + SMAX_PR_OFF);

    const int bh = blockIdx.x;
    const int b  = bh / H_;
    const int h  = bh - b * H_;
    const int tid = threadIdx.x;

    const float* vb = g_v + (size_t)bh * N_ * HD_;
    for (int i = tid; i < (N_ * HD_) / 4; i += 256)
        reinterpret_cast<float4*>(Vs)[i] = reinterpret_cast<const float4*>(vb)[i];
    for (int i = tid; i < N_; i += 256) msk[i] = g_mask[b * N_ + i];
    __syncthreads();

    const int w = tid >> 5, lane = tid & 31;
    const float* ab = attn + (size_t)bh * N_ * N_;
    uint2* prw = pr + w * 200;

    for (int base = w * 4; base < N_; base += 32) {
        float xv[4][7];
        float mx[4] = {-1e30f, -1e30f, -1e30f, -1e30f};
#pragma unroll
        for (int r = 0; r < 4; r++) {
            int row = base + r;
            const float* arow = ab + (size_t)row * N_;
#pragma unroll
            for (int t = 0; t < 7; t++) {
                int j = lane + t * 32;
                float x = (row < N_ && j < N_) ? (arow[j] + msk[j]) : -1e30f;
                xv[r][t] = x;
                mx[r] = fmaxf(mx[r], x);
            }
        }
#pragma unroll
        for (int r = 0; r < 4; r++)
            for (int o = 16; o > 0; o >>= 1)
                mx[r] = fmaxf(mx[r], __shfl_xor_sync(0xffffffffu, mx[r], o));

        float sum[4] = {0.f, 0.f, 0.f, 0.f};
#pragma unroll
        for (int t = 0; t < 7; t++) {
            int j = lane + t * 32;
            float t0 = (xv[0][t] - mx[0]) * LOG2E_;
            float t1 = (xv[1][t] - mx[1]) * LOG2E_;
            float t2 = (xv[2][t] - mx[2]) * LOG2E_;
            float t3 = (xv[3][t] - mx[3]) * LOG2E_;
            uint32_t p01 = ex2_f16x2(t0, t1);
            uint32_t p23 = ex2_f16x2(t2, t3);
            __half2 h01 = *reinterpret_cast<__half2*>(&p01);
            __half2 h23 = *reinterpret_cast<__half2*>(&p23);
            float2 f01 = __half22float2(h01);
            float2 f23 = __half22float2(h23);
            sum[0] += f01.x; sum[1] += f01.y;
            sum[2] += f23.x; sum[3] += f23.y;
            if (j < N_) prw[j] = make_uint2(p01, p23);
        }
#pragma unroll
        for (int r = 0; r < 4; r++)
            for (int o = 16; o > 0; o >>= 1)
                sum[r] += __shfl_xor_sync(0xffffffffu, sum[r], o);

        __syncwarp();

        float acc0[4] = {0.f,0.f,0.f,0.f}, acc1[4] = {0.f,0.f,0.f,0.f};
        for (int j = 0; j < N_; j++) {
            uint2 pq = prw[j];
            __half2 h01 = *reinterpret_cast<__half2*>(&pq.x);
            __half2 h23 = *reinterpret_cast<__half2*>(&pq.y);
            float2 f01 = __half22float2(h01);
            float2 f23 = __half22float2(h23);
            float v0 = Vs[j * HD_ + lane];
            float v1 = Vs[j * HD_ + lane + 32];
            acc0[0] += f01.x * v0; acc1[0] += f01.x * v1;
            acc0[1] += f01.y * v0; acc1[1] += f01.y * v1;
            acc0[2] += f23.x * v0; acc1[2] += f23.x * v1;
            acc0[3] += f23.y * v0; acc1[3] += f23.y * v1;
        }
#pragma unroll
        for (int r = 0; r < 4; r++) {
            int row = base + r;
            if (row >= N_) continue;
            float inv = 1.f / sum[r];
            size_t o = ((size_t)(b * N_ + row) * H_ + h) * HD_;
            g_ctx[o + lane]      = acc0[r] * inv;
            g_ctx[o + lane + 32] = acc1[r] * inv;
        }
        __syncwarp();
    }
}

// ---------------- launch ----------------
extern "C" void kernel_launch(void* const* d_in, const int* in_sizes, int n_in,
                              void* d_out, int out_size)
{
    const float* x      = (const float*)d_in[0];
    const float* qkv_w  = (const float*)d_in[1];
    const float* qkv_b  = (const float*)d_in[2];
    const float* proj_w = (const float*)d_in[3];
    const float* proj_b = (const float*)d_in[4];
    const int*   nkeep  = (const int*)  d_in[5];

    float* out       = (float*)d_out;                       // [B,N,C]
    float* keep_mask = out + (size_t)MROWS * C_;            // [B,N,1]
    float* attn      = keep_mask + MROWS;                   // [B,H,N,N]

    cudaFuncSetAttribute((const void*)softmax_av,
                         cudaFuncAttributeMaxDynamicSharedMemorySize, SMAX_SMEM_BYTES);
    cudaFuncSetAttribute((const void*)gemm_mma<0>,
                         cudaFuncAttributeMaxDynamicSharedMemorySize, GEMM_SMEM_BYTES);
    cudaFuncSetAttribute((const void*)gemm_mma<1>,
                         cudaFuncAttributeMaxDynamicSharedMemorySize, GEMM_SMEM_BYTES);
    cudaFuncSetAttribute((const void*)attn_scores_mma,
                         cudaFuncAttributeMaxDynamicSharedMemorySize, ATTN_SMEM_BYTES);

    // 1) qkv GEMM (fp16-split mma) -> g_q (scaled), g_k, g_v
    gemm_mma<0><<<dim3((3 * C_) / 128, (MROWS + 127) / 128), 256, GEMM_SMEM_BYTES>>>(
        x, qkv_w, qkv_b, nullptr, MROWS, 3 * C_, C_);

    // 2) attn_rt = q @ k^T (fp16-split mma), written into output region
    attn_scores_mma<<<dim3(2, BH_), 256, ATTN_SMEM_BYTES>>>(attn);

    // 3) cls mean + top-k -> additive mask + keep_mask output
    topk_mask<<<B_, 256>>>(attn, keep_mask, nkeep);

    // 4) masked softmax (fp16x2 exp) + attn @ V -> g_ctx
    softmax_av<<<BH_, 256, SMAX_SMEM_BYTES>>>(attn);

    // 5) proj GEMM (fp16-split mma) -> out
    gemm_mma<1><<<dim3(C_ / 128, (MROWS + 127) / 128), 256, GEMM_SMEM_BYTES>>>(
        nullptr, proj_w, proj_b, out, MROWS, C_, C_);
}